// round 4
// baseline (speedup 1.0000x reference)
#include <cuda_runtime.h>
#include <cstdint>

// S4D Vandermonde kernel:  K[h,l] = 2 * sum_n C_eff[h,n] * exp(dtA[h,n] * l)
// H=256, NH=N/2=32, L=16384.
//
// With this problem's init dtA[h,n] is constant across n, so
// K[h,l] = S[h] * exp(dtA[h]*l): one geometric recurrence per head.
// R4 structure (fixing the R3 occupancy/latency diagnosis):
//   A) setup kernel: warp<->head, lane<->n. Per-head {S,dtA0,q1,stp} + a
//      bitwise-uniformity flag into __device__ scratch.
//   B) fast writer: no smem/sync/fallback-arrays -> low regs, high occupancy,
//      one LDG.128 + one MUFU prologue, then float4 geometric stores.
//   C) generic fallback kernel (32-chain f32x2): early-exits per head when
//      the uniform flag is set, so its register cost is only paid when used.

#define TPB  256
#define NH   32
#define TILE 4096          // l-elements per block (kernels B and C)
#define TG   16            // generic path: strided elems/thread
#define JF   4             // fast path: 4 float4 stores/thread (4*4*256=4096)
#define MAXH 1024

__device__ float4 g_params[MAXH];   // {S, dtA0, q1=exp(dtA0), stp=exp(dtA0*1024)}
__device__ int    g_uok[MAXH];      // per-head: dtA bitwise-uniform across n

typedef unsigned long long ull;

__device__ __forceinline__ ull fma2(ull a, ull b, ull c) {
    ull d; asm("fma.rn.f32x2 %0, %1, %2, %3;" : "=l"(d) : "l"(a), "l"(b), "l"(c));
    return d;
}
__device__ __forceinline__ ull mul2(ull a, ull b) {
    ull d; asm("mul.rn.f32x2 %0, %1, %2;" : "=l"(d) : "l"(a), "l"(b));
    return d;
}
__device__ __forceinline__ ull pack2(float lo, float hi) {
    ull u; asm("mov.b64 %0, {%1, %2};" : "=l"(u) : "f"(lo), "f"(hi));
    return u;
}
__device__ __forceinline__ void unpack2(ull u, float& lo, float& hi) {
    asm("mov.b64 {%0, %1}, %2;" : "=f"(lo), "=f"(hi) : "l"(u));
}

// ---------------- Kernel A: per-head setup (warp == head, lane == n) --------
__global__ void __launch_bounds__(TPB) s4d_setup(
    const float* __restrict__ log_dt,
    const float* __restrict__ C,
    const float* __restrict__ log_A_real,
    const float* __restrict__ A_imag,
    int H)
{
    const int w    = (blockIdx.x * TPB + threadIdx.x) >> 5;   // head
    const int lane = threadIdx.x & 31;                        // n
    if (w >= H) return;

    float dt   = expf(log_dt[w]);                     // broadcast LDG
    float Ar   = -expf(log_A_real[w * NH + lane]);
    float Ai   = A_imag[w * NH + lane];
    float dtA  = Ar * dt;
    float den  = Ar * Ar + Ai * Ai;
    // exactly mirrors reference fp32 math: 2*C*(exp(dtA)-1)*Ar/den
    float c    = 2.0f * C[w * NH + lane] * (expf(dtA) - 1.0f) * Ar / den;

    float dtA0  = __shfl_sync(0xffffffffu, dtA, 0);
    unsigned eq = __ballot_sync(0xffffffffu,
                    __float_as_uint(dtA) == __float_as_uint(dtA0));
#pragma unroll
    for (int o = 16; o; o >>= 1)
        c += __shfl_xor_sync(0xffffffffu, c, o);

    if (lane == 0) {
        g_params[w] = make_float4(c, dtA0, __expf(dtA0),
                                  __expf(dtA0 * (float)(4 * TPB)));
        g_uok[w] = (eq == 0xffffffffu);
    }
}

// ---------------- Kernel B: fast writer  K[h,l] = S * exp(dtA0*l) -----------
__global__ void __launch_bounds__(TPB) s4d_fast(
    float* __restrict__ out, int L)
{
    const int h = blockIdx.y;
    if (!g_uok[h]) return;                 // generic kernel owns this head

    const float4 P  = g_params[h];         // {S, dtA0, q1, stp} LDG.128 bcast
    const int    l0 = blockIdx.x * TILE;
    const int    t  = threadIdx.x;

    const float lb = (float)(l0 + 4 * t);
    float p0 = __expf(P.y * lb);           // the one per-thread MUFU
    float p1 = p0 * P.z;
    float p2 = p1 * P.z;
    float p3 = p2 * P.z;

    ull pa = pack2(p0, p1);
    ull pb = pack2(p2, p3);
    const ull s2  = pack2(P.x, P.x);
    const ull st2 = pack2(P.w, P.w);

    float4* o = (float4*)(out + (size_t)h * L + l0) + t;
#pragma unroll
    for (int j = 0; j < JF; j++) {
        ull va = mul2(pa, s2);
        ull vb = mul2(pb, s2);
        float4 v;
        unpack2(va, v.x, v.y);
        unpack2(vb, v.z, v.w);
        if (l0 + 4 * t + j * 4 * TPB + 3 < L) o[j * TPB] = v;
        pa = mul2(pa, st2);
        pb = mul2(pb, st2);
    }
}

// ---------------- Kernel C: generic fallback (32 geometric chains) ----------
__global__ void __launch_bounds__(TPB) s4d_generic(
    const float* __restrict__ log_dt,
    const float* __restrict__ C,
    const float* __restrict__ log_A_real,
    const float* __restrict__ A_imag,
    float* __restrict__ out, int L)
{
    const int h = blockIdx.y;
    if (g_uok[h]) return;                  // fast kernel owned this head

    const int l0 = blockIdx.x * TILE;
    const int t  = threadIdx.x;

    __shared__ float s_c[NH];
    __shared__ float s_dtA[NH];

    if (t < NH) {
        float dt   = expf(log_dt[h]);
        float Ar   = -expf(log_A_real[h * NH + t]);
        float Ai   = A_imag[h * NH + t];
        float dtA  = Ar * dt;
        float den  = Ar * Ar + Ai * Ai;
        s_c[t]   = 2.0f * C[h * NH + t] * (expf(dtA) - 1.0f) * Ar / den;
        s_dtA[t] = dtA;
    }
    __syncthreads();

    const float lstart = (float)(l0 + t);
    ull p[NH / 2], r[NH / 2], c[NH / 2];
#pragma unroll
    for (int i = 0; i < NH / 2; i++) {
        float d0 = s_dtA[2 * i], d1 = s_dtA[2 * i + 1];
        p[i] = pack2(__expf(d0 * lstart), __expf(d1 * lstart));
        r[i] = pack2(__expf(d0 * (float)TPB), __expf(d1 * (float)TPB));
        c[i] = pack2(s_c[2 * i], s_c[2 * i + 1]);
    }

    float* o = out + (size_t)h * L + l0 + t;
    const int lim = L - l0 - t;
#pragma unroll
    for (int j = 0; j < TG; j++) {
        ull a0 = 0ull, a1 = 0ull, a2 = 0ull, a3 = 0ull;
#pragma unroll
        for (int i = 0; i < NH / 2; i += 4) {
            a0       = fma2(c[i],     p[i],     a0);
            p[i]     = mul2(p[i],     r[i]);
            a1       = fma2(c[i + 1], p[i + 1], a1);
            p[i + 1] = mul2(p[i + 1], r[i + 1]);
            a2       = fma2(c[i + 2], p[i + 2], a2);
            p[i + 2] = mul2(p[i + 2], r[i + 2]);
            a3       = fma2(c[i + 3], p[i + 3], a3);
            p[i + 3] = mul2(p[i + 3], r[i + 3]);
        }
        float x0, y0, x1, y1, x2, y2, x3, y3;
        unpack2(a0, x0, y0); unpack2(a1, x1, y1);
        unpack2(a2, x2, y2); unpack2(a3, x3, y3);
        float v = ((x0 + y0) + (x1 + y1)) + ((x2 + y2) + (x3 + y3));
        if (j * TPB < lim) o[j * TPB] = v;
    }
}

extern "C" void kernel_launch(void* const* d_in, const int* in_sizes, int n_in,
                              void* d_out, int out_size)
{
    const float* log_dt     = (const float*)d_in[0];
    const float* C          = (const float*)d_in[1];
    const float* log_A_real = (const float*)d_in[2];
    const float* A_imag     = (const float*)d_in[3];
    float* out = (float*)d_out;

    const int H = in_sizes[0];
    const int L = out_size / H;

    const int setup_blocks = (H * 32 + TPB - 1) / TPB;
    s4d_setup<<<setup_blocks, TPB>>>(log_dt, C, log_A_real, A_imag, H);

    dim3 grid((L + TILE - 1) / TILE, H);
    s4d_fast<<<grid, TPB>>>(out, L);
    s4d_generic<<<grid, TPB>>>(log_dt, C, log_A_real, A_imag, out, L);
}

// round 5
// speedup vs baseline: 1.2610x; 1.2610x over previous
#include <cuda_runtime.h>
#include <cstdint>

// S4D Vandermonde kernel:  K[h,l] = 2 * sum_n C_eff[h,n] * exp(dtA[h,n] * l)
// H=256, NH=N/2=32, L=16384.
//
// With this problem's init dtA[h,n] is constant across n, so
// K[h,l] = S[h] * exp(dtA[h]*l): one geometric recurrence per head.
// R5 structure: ONE kernel, warp-autonomous (R4's 3-node split paid ~5us of
// launch/ramp tax). Each warp owns a (head, 1024-elem chunk); lane=n does the
// per-head param math, ballot checks bitwise n-uniformity of dtA, shfl-reduce
// gives S. Hot path: 1 MUFU seed + 8x(2 mul.f32x2 + STG.128). Cold fallback
// (non-uniform dtA) is an in-kernel shfl-gather direct evaluation, written
// register-light so it doesn't bloat the hot path's allocation.

#define TPB    256
#define NH     32
#define WPB    (TPB / 32)      // warps per block
#define JF     8               // float4 stores per lane
#define WCHUNK (32 * 4 * JF)   // 1024 l-elements per warp

typedef unsigned long long ull;

__device__ __forceinline__ ull mul2(ull a, ull b) {
    ull d; asm("mul.rn.f32x2 %0, %1, %2;" : "=l"(d) : "l"(a), "l"(b));
    return d;
}
__device__ __forceinline__ ull pack2(float lo, float hi) {
    ull u; asm("mov.b64 %0, {%1, %2};" : "=l"(u) : "f"(lo), "f"(hi));
    return u;
}
__device__ __forceinline__ void unpack2(ull u, float& lo, float& hi) {
    asm("mov.b64 {%0, %1}, %2;" : "=f"(lo), "=f"(hi) : "l"(u));
}

__global__ void __launch_bounds__(TPB) s4d_kernel(
    const float* __restrict__ log_dt,      // [H]
    const float* __restrict__ C,           // [H, NH]
    const float* __restrict__ log_A_real,  // [H, NH]
    const float* __restrict__ A_imag,      // [H, NH]
    float* __restrict__ out,               // [H, L]
    int L)
{
    const int h     = blockIdx.y;
    const int lane  = threadIdx.x & 31;
    const int chunk = blockIdx.x * WPB + (threadIdx.x >> 5);
    const int cbase = chunk * WCHUNK;
    if (cbase >= L) return;

    // ---- per-warp setup: lane == n (coefficient math mirrors reference fp32) ----
    float dt   = expf(log_dt[h]);
    float Ar   = -expf(log_A_real[h * NH + lane]);
    float Ai   = A_imag[h * NH + lane];
    float dtA  = Ar * dt;
    float den  = Ar * Ar + Ai * Ai;
    float c    = 2.0f * C[h * NH + lane] * (expf(dtA) - 1.0f) * Ar / den;

    const float dtA0  = __shfl_sync(0xffffffffu, dtA, 0);
    const unsigned eq = __ballot_sync(0xffffffffu,
                          __float_as_uint(dtA) == __float_as_uint(dtA0));
    float S = c;
#pragma unroll
    for (int o = 16; o; o >>= 1)
        S += __shfl_xor_sync(0xffffffffu, S, o);

    float* obase = out + (size_t)h * L + cbase;

    if (eq == 0xffffffffu) {
        // ---- hot path: K = S * exp(dtA0 * l), geometric recurrence ----
        const float q1  = __expf(dtA0);                 // adjacent-l ratio
        const float stp = __expf(dtA0 * 128.0f);        // j-step ratio (32 lanes * 4)
        float p0 = __expf(dtA0 * (float)(cbase + 4 * lane));
        float p1 = p0 * q1;
        float p2 = p1 * q1;
        float p3 = p2 * q1;

        ull pa = pack2(p0, p1);
        ull pb = pack2(p2, p3);
        const ull s2  = pack2(S, S);
        const ull st2 = pack2(stp, stp);

        float4* o = (float4*)(obase) + lane;
        const int lrem = cbase + 4 * lane;
#pragma unroll
        for (int j = 0; j < JF; j++) {
            ull va = mul2(pa, s2);
            ull vb = mul2(pb, s2);
            float4 v;
            unpack2(va, v.x, v.y);
            unpack2(vb, v.z, v.w);
            if (lrem + j * 128 + 3 < L) o[j * 32] = v;
            pa = mul2(pa, st2);
            pb = mul2(pb, st2);
        }
    } else {
        // ---- cold path: direct evaluation via shfl-gathered coefficients ----
        // lane handles l = cbase + lane + k*32, k < WCHUNK/32.
        for (int k = 0; k < WCHUNK / 32; k++) {
            const int l = cbase + lane + k * 32;
            float lf = (float)l;
            float acc = 0.0f;
#pragma unroll
            for (int i = 0; i < NH; i++) {
                float ci = __shfl_sync(0xffffffffu, c,   i);
                float di = __shfl_sync(0xffffffffu, dtA, i);
                acc += ci * __expf(di * lf);
            }
            if (l < L) obase[lane + k * 32] = acc;
        }
    }
}

extern "C" void kernel_launch(void* const* d_in, const int* in_sizes, int n_in,
                              void* d_out, int out_size)
{
    const float* log_dt     = (const float*)d_in[0];
    const float* C          = (const float*)d_in[1];
    const float* log_A_real = (const float*)d_in[2];
    const float* A_imag     = (const float*)d_in[3];
    float* out = (float*)d_out;

    const int H = in_sizes[0];
    const int L = out_size / H;

    const int chunks = (L + WCHUNK - 1) / WCHUNK;       // warps per head
    dim3 grid((chunks + WPB - 1) / WPB, H);
    s4d_kernel<<<grid, TPB>>>(log_dt, C, log_A_real, A_imag, out, L);
}

// round 6
// speedup vs baseline: 1.3295x; 1.0543x over previous
#include <cuda_runtime.h>
#include <cstdint>

// S4D Vandermonde kernel:  K[h,l] = 2 * sum_n C_eff[h,n] * exp(dtA[h,n] * l)
// H=256, NH=N/2=32, L=16384.
//
// With this problem's init dtA[h,n] is constant across n, so
// K[h,l] = S[h] * exp(dtA[h]*l): one geometric recurrence per head.
// Warp-autonomous: each warp owns a (head, 512-elem chunk); lane=n computes
// per-head params, ballot checks bitwise n-uniformity of dtA, shfl-reduce
// gives S. R6 changes vs R5: __expf (MUFU) replaces library expf in the
// prologue (shorter serial chain), WCHUNK 1024->512 doubles resident warps
// (occupancy 43%->86% of max) to hide the prologue latency, and full tiles
// store unconditionally.

#define TPB    256
#define NH     32
#define WPB    (TPB / 32)      // warps per block
#define JF     4               // float4 stores per lane
#define WCHUNK (32 * 4 * JF)   // 512 l-elements per warp

typedef unsigned long long ull;

__device__ __forceinline__ ull mul2(ull a, ull b) {
    ull d; asm("mul.rn.f32x2 %0, %1, %2;" : "=l"(d) : "l"(a), "l"(b));
    return d;
}
__device__ __forceinline__ ull pack2(float lo, float hi) {
    ull u; asm("mov.b64 %0, {%1, %2};" : "=l"(u) : "f"(lo), "f"(hi));
    return u;
}
__device__ __forceinline__ void unpack2(ull u, float& lo, float& hi) {
    asm("mov.b64 {%0, %1}, %2;" : "=f"(lo), "=f"(hi) : "l"(u));
}

__global__ void __launch_bounds__(TPB) s4d_kernel(
    const float* __restrict__ log_dt,      // [H]
    const float* __restrict__ C,           // [H, NH]
    const float* __restrict__ log_A_real,  // [H, NH]
    const float* __restrict__ A_imag,      // [H, NH]
    float* __restrict__ out,               // [H, L]
    int L)
{
    const int h     = blockIdx.y;
    const int lane  = threadIdx.x & 31;
    const int chunk = blockIdx.x * WPB + (threadIdx.x >> 5);
    const int cbase = chunk * WCHUNK;
    if (cbase >= L) return;

    // ---- per-warp setup: lane == n. __expf (MUFU) keeps the chain short;
    // rel err ~2^-21 vs the 1e-3 gate. Math mirrors the reference fp32 form.
    float dt   = __expf(log_dt[h]);
    float Ar   = -__expf(log_A_real[h * NH + lane]);
    float Ai   = A_imag[h * NH + lane];
    float dtA  = Ar * dt;
    float den  = Ar * Ar + Ai * Ai;
    float c    = 2.0f * C[h * NH + lane] * (__expf(dtA) - 1.0f) * Ar / den;

    const float dtA0  = __shfl_sync(0xffffffffu, dtA, 0);
    const unsigned eq = __ballot_sync(0xffffffffu,
                          __float_as_uint(dtA) == __float_as_uint(dtA0));
    float S = c;
#pragma unroll
    for (int o = 16; o; o >>= 1)
        S += __shfl_xor_sync(0xffffffffu, S, o);

    float* obase = out + (size_t)h * L + cbase;

    if (eq == 0xffffffffu) {
        // ---- hot path: K = S * exp(dtA0 * l), geometric recurrence ----
        const float q1  = __expf(dtA0);            // adjacent-l ratio
        const float stp = __expf(dtA0 * 128.0f);   // j-step ratio (32 lanes * 4)
        float p0 = __expf(dtA0 * (float)(cbase + 4 * lane));
        float p1 = p0 * q1;
        float p2 = p1 * q1;
        float p3 = p2 * q1;

        ull pa = pack2(p0, p1);
        ull pb = pack2(p2, p3);
        const ull s2  = pack2(S, S);
        const ull st2 = pack2(stp, stp);

        float4* o = (float4*)(obase) + lane;
        if (cbase + WCHUNK <= L) {
#pragma unroll
            for (int j = 0; j < JF; j++) {
                ull va = mul2(pa, s2);
                ull vb = mul2(pb, s2);
                float4 v;
                unpack2(va, v.x, v.y);
                unpack2(vb, v.z, v.w);
                o[j * 32] = v;                       // unconditional
                pa = mul2(pa, st2);
                pb = mul2(pb, st2);
            }
        } else {
            const int lrem = cbase + 4 * lane;
#pragma unroll
            for (int j = 0; j < JF; j++) {
                ull va = mul2(pa, s2);
                ull vb = mul2(pb, s2);
                float4 v;
                unpack2(va, v.x, v.y);
                unpack2(vb, v.z, v.w);
                if (lrem + j * 128 + 3 < L) o[j * 32] = v;
                pa = mul2(pa, st2);
                pb = mul2(pb, st2);
            }
        }
    } else {
        // ---- cold path: direct evaluation via shfl-gathered coefficients ----
        for (int k = 0; k < WCHUNK / 32; k++) {
            const int l = cbase + lane + k * 32;
            float lf = (float)l;
            float acc = 0.0f;
#pragma unroll
            for (int i = 0; i < NH; i++) {
                float ci = __shfl_sync(0xffffffffu, c,   i);
                float di = __shfl_sync(0xffffffffu, dtA, i);
                acc += ci * __expf(di * lf);
            }
            if (l < L) obase[lane + k * 32] = acc;
        }
    }
}

extern "C" void kernel_launch(void* const* d_in, const int* in_sizes, int n_in,
                              void* d_out, int out_size)
{
    const float* log_dt     = (const float*)d_in[0];
    const float* C          = (const float*)d_in[1];
    const float* log_A_real = (const float*)d_in[2];
    const float* A_imag     = (const float*)d_in[3];
    float* out = (float*)d_out;

    const int H = in_sizes[0];
    const int L = out_size / H;

    const int chunks = (L + WCHUNK - 1) / WCHUNK;       // warps per head
    dim3 grid((chunks + WPB - 1) / WPB, H);
    s4d_kernel<<<grid, TPB>>>(log_dt, C, log_A_real, A_imag, out, L);
}